// round 16
// baseline (speedup 1.0000x reference)
#include <cuda_runtime.h>
#include <cuda_fp16.h>
#include <math_constants.h>
#include <cstdint>

#define Bb 16
#define Ss 2048
#define Hh 1024
#define Mm (Bb * Ss)   // 32768

#define NCH 64           // context S-chunks
__device__ float g_q[Bb * Hh];
__device__ float g_ctx_part[16 * NCH * 1024];
__device__ __half g_Ah[(size_t)Mm * Hh];   // fp16 copy of encoder_outputs (64 MB)
__device__ __half g_Wh[(size_t)Hh * Hh];   // fp16 copy of Wa (2 MB)

// ---------------------------------------------------------------- helpers
__device__ __forceinline__ uint32_t smem_u32(const void* p) {
    uint32_t a;
    asm("{ .reg .u64 t; cvta.to.shared.u64 t, %1; cvt.u32.u64 %0, t; }" : "=r"(a) : "l"(p));
    return a;
}
__device__ __forceinline__ void cp_async16(uint32_t dst, const void* src) {
    asm volatile("cp.async.cg.shared.global [%0], [%1], 16;" :: "r"(dst), "l"(src));
}
__device__ __forceinline__ void cp_commit() { asm volatile("cp.async.commit_group;"); }
__device__ __forceinline__ void cp_wait1()  { asm volatile("cp.async.wait_group 1;"); }
__device__ __forceinline__ void cp_wait0()  { asm volatile("cp.async.wait_group 0;"); }

__device__ __forceinline__ void ldsm_x4(uint32_t* r, uint32_t addr) {
    asm volatile("ldmatrix.sync.aligned.m8n8.x4.shared.b16 {%0,%1,%2,%3}, [%4];"
                 : "=r"(r[0]), "=r"(r[1]), "=r"(r[2]), "=r"(r[3]) : "r"(addr));
}

__device__ __forceinline__ void mma_fp16(float* d, const uint32_t* a, uint32_t b0, uint32_t b1) {
    asm volatile(
        "mma.sync.aligned.m16n8k16.row.col.f32.f16.f16.f32 "
        "{%0,%1,%2,%3}, {%4,%5,%6,%7}, {%8,%9}, {%0,%1,%2,%3};"
        : "+f"(d[0]), "+f"(d[1]), "+f"(d[2]), "+f"(d[3])
        : "r"(a[0]), "r"(a[1]), "r"(a[2]), "r"(a[3]), "r"(b0), "r"(b1));
}

// ---------------------------------------------------------------------------
// Kernel 0: fused prep — convert A & Wa to fp16, compute q, zero scores.
// Flattened grid: [0, Mm) convA; [Mm, Mm+Hh) convW; then q (Bb*Hh/8) and
// zero (Bb*2) blocks. 256 threads each.
// ---------------------------------------------------------------------------
#define NCONV_A Mm                 // 32768 blocks
#define NCONV_W Hh                 // 1024 blocks
#define NQ (Bb * (Hh / 8))         // 2048 blocks
#define NZ (Bb * 2)                // 32 blocks

__global__ void prep_kernel(const float* __restrict__ A,
                            const float* __restrict__ W,
                            const float* __restrict__ h,
                            const float* __restrict__ bias,
                            float* __restrict__ scores) {
    int bid = blockIdx.x;
    if (bid < NCONV_A) {
        size_t i = ((size_t)bid * 256 + threadIdx.x) * 4;
        float4 v = *(const float4*)(A + i);
        *(__half2*)(g_Ah + i)     = __floats2half2_rn(v.x, v.y);
        *(__half2*)(g_Ah + i + 2) = __floats2half2_rn(v.z, v.w);
        return;
    }
    bid -= NCONV_A;
    if (bid < NCONV_W) {
        int idx = bid * 256 + threadIdx.x;
        int row = idx >> 8;
        int col = (idx & 255) * 4;
        float4 v = *(const float4*)(W + (size_t)row * (2 * Hh) + Hh + col);
        *(__half2*)(g_Wh + (size_t)row * Hh + col)     = __floats2half2_rn(v.x, v.y);
        *(__half2*)(g_Wh + (size_t)row * Hh + col + 2) = __floats2half2_rn(v.z, v.w);
        return;
    }
    bid -= NCONV_W;
    if (bid < NQ) {
        int b = bid >> 7;              // /(Hh/8)
        int y = bid & 127;
        __shared__ float hs[Hh];
        for (int i = threadIdx.x; i < Hh; i += blockDim.x) hs[i] = h[b * Hh + i];
        __syncthreads();
        int warp = threadIdx.x >> 5, lane = threadIdx.x & 31;
        int o = y * 8 + warp;
        const float* Wrow = W + (size_t)o * (2 * Hh);
        float acc = 0.f;
        #pragma unroll 8
        for (int k = lane; k < Hh; k += 32) acc += hs[k] * Wrow[k];
        #pragma unroll
        for (int off = 16; off; off >>= 1) acc += __shfl_xor_sync(0xffffffffu, acc, off);
        if (lane == 0) g_q[b * Hh + o] = acc + bias[o];
        return;
    }
    bid -= NQ;
    {   // zero scores
        int b = bid >> 1, part = bid & 1;
        size_t base = (size_t)b * Ss + part * 1024;
        for (int i = threadIdx.x; i < 1024; i += blockDim.x) scores[base + i] = 0.f;
    }
}

// ---------------------------------------------------------------------------
// Kernel 2: fused scores GEMM, fp16 mma.sync m16n8k16, BK=64 (half barriers).
// CTA = 256 threads (8 warps), tile 128x128, warp tile 32x64 (4x2).
// 2-stage cp.async, PADH=72 halves (144B stride — LDSM conflict-free).
// Epilogue: relu(+q)*v row-reduction, atomicAdd row partials.
// ---------------------------------------------------------------------------
#define BKI 64
#define PADH 72
#define NIT (Hh / BKI)                 // 16
#define TAH (128 * PADH)               // tile halves per matrix (9216)
#define TA_B (TAH * 2)                 // 18432 bytes
#define STAGE_B (2 * TA_B)             // A + B (36864 bytes)
#define SC_SMEM (2 * STAGE_B)          // 73728 bytes

__global__ void __launch_bounds__(256, 2)
scores_mma(const float* __restrict__ v,
           float* __restrict__ out_scores) {
    extern __shared__ __half smh[];
    __shared__ float s_q[128];
    __shared__ float s_v[128];

    const int tid  = threadIdx.x;
    const int wid  = tid >> 5, lane = tid & 31;
    const int g    = lane >> 2, t = lane & 3;
    const int bm   = blockIdx.x;          // m block (128 rows) — fastest
    const int bn   = blockIdx.y;          // n block (128 cols)
    const int b    = (bm * 128) >> 11;    // batch
    const int wm   = (wid & 3) * 32;      // warp m offset
    const int wn   = (wid >> 2) * 64;     // warp n offset

    if (tid < 128) {
        s_q[tid] = g_q[b * Hh + bn * 128 + tid];
        s_v[tid] = v[bn * 128 + tid];
    }

    const uint32_t smBase = smem_u32(smh);

    // cp.async: row = tid>>1 (0..127), half-row = tid&1 (64B each),
    // 4 chunks of 16B per half-row, for A and B each.
    const int r0 = tid >> 1, hf = tid & 1;
    const __half* aG = g_Ah + (size_t)(bm * 128 + r0) * Hh + hf * 32;
    const __half* bG = g_Wh + (size_t)(bn * 128 + r0) * Hh + hf * 32;
    const uint32_t aSm = smBase + r0 * (PADH * 2) + hf * 64;
    const uint32_t bSm = smBase + TA_B + r0 * (PADH * 2) + hf * 64;

    // LDSM bases
    const uint32_t aAddr = smBase + (wm + (lane & 15)) * (PADH * 2) + (lane >> 4) * 16;
    const uint32_t bAddr = smBase + TA_B + (wn + (lane & 15)) * (PADH * 2) + (lane >> 4) * 16;

    auto load_stage = [&](int s, int k0) {
        const uint32_t so = s * STAGE_B;
        const __half* ag = aG + k0;
        const __half* bg = bG + k0;
        #pragma unroll
        for (int i = 0; i < 4; i++) cp_async16(aSm + so + i * 16, ag + i * 8);
        #pragma unroll
        for (int i = 0; i < 4; i++) cp_async16(bSm + so + i * 16, bg + i * 8);
        cp_commit();
    };

    float acc[2][8][4] = {};

    load_stage(0, 0);

    for (int it = 0; it < NIT; it++) {
        const int buf = it & 1;
        if (it + 1 < NIT) { load_stage(buf ^ 1, (it + 1) * BKI); cp_wait1(); }
        else              { cp_wait0(); }
        __syncthreads();

        const uint32_t aB = aAddr + buf * STAGE_B;
        const uint32_t bB = bAddr + buf * STAGE_B;

        #pragma unroll
        for (int ks = 0; ks < 4; ks++) {
            const uint32_t ko = ks * 32;           // 16 halves per k-step
            uint32_t a0[4], a1[4], b0[4], b1[4], b2[4], b3[4];
            ldsm_x4(a0, aB + ko);
            ldsm_x4(a1, aB + ko + 16 * (PADH * 2));
            ldsm_x4(b0, bB + ko);
            ldsm_x4(b1, bB + ko + 16 * (PADH * 2));
            ldsm_x4(b2, bB + ko + 32 * (PADH * 2));
            ldsm_x4(b3, bB + ko + 48 * (PADH * 2));

            mma_fp16(acc[0][0], a0, b0[0], b0[2]);  mma_fp16(acc[1][0], a1, b0[0], b0[2]);
            mma_fp16(acc[0][1], a0, b0[1], b0[3]);  mma_fp16(acc[1][1], a1, b0[1], b0[3]);
            mma_fp16(acc[0][2], a0, b1[0], b1[2]);  mma_fp16(acc[1][2], a1, b1[0], b1[2]);
            mma_fp16(acc[0][3], a0, b1[1], b1[3]);  mma_fp16(acc[1][3], a1, b1[1], b1[3]);
            mma_fp16(acc[0][4], a0, b2[0], b2[2]);  mma_fp16(acc[1][4], a1, b2[0], b2[2]);
            mma_fp16(acc[0][5], a0, b2[1], b2[3]);  mma_fp16(acc[1][5], a1, b2[1], b2[3]);
            mma_fp16(acc[0][6], a0, b3[0], b3[2]);  mma_fp16(acc[1][6], a1, b3[0], b3[2]);
            mma_fp16(acc[0][7], a0, b3[1], b3[3]);  mma_fp16(acc[1][7], a1, b3[1], b3[3]);
        }
        __syncthreads();
    }

    // epilogue: relu(+q)*v, reduce cols
    float rs[2][2] = {};
    #pragma unroll
    for (int j = 0; j < 8; j++) {
        const int nl = wn + j * 8 + 2 * t;
        const float q0 = s_q[nl], q1 = s_q[nl + 1];
        const float v0 = s_v[nl], v1 = s_v[nl + 1];
        #pragma unroll
        for (int i = 0; i < 2; i++) {
            rs[i][0] += fmaxf(acc[i][j][0] + q0, 0.f) * v0 + fmaxf(acc[i][j][1] + q1, 0.f) * v1;
            rs[i][1] += fmaxf(acc[i][j][2] + q0, 0.f) * v0 + fmaxf(acc[i][j][3] + q1, 0.f) * v1;
        }
    }
    #pragma unroll
    for (int off = 1; off < 4; off <<= 1) {
        #pragma unroll
        for (int i = 0; i < 2; i++) {
            rs[i][0] += __shfl_xor_sync(0xffffffffu, rs[i][0], off);
            rs[i][1] += __shfl_xor_sync(0xffffffffu, rs[i][1], off);
        }
    }
    if (t == 0) {
        const int rowb = bm * 128 + wm;
        #pragma unroll
        for (int i = 0; i < 2; i++) {
            atomicAdd(&out_scores[rowb + i * 16 + g    ], rs[i][0]);
            atomicAdd(&out_scores[rowb + i * 16 + g + 8], rs[i][1]);
        }
    }
}

// ---------------------------------------------------------------------------
// Kernel 3: in-place softmax over S per batch. grid 16, block 1024.
// ---------------------------------------------------------------------------
__global__ void softmax_kernel(float* __restrict__ w) {
    int b = blockIdx.x;
    float* row = w + (size_t)b * Ss;
    __shared__ float red[1024];
    int tid = threadIdx.x;

    float m = fmaxf(row[tid], row[tid + 1024]);
    red[tid] = m; __syncthreads();
    for (int s = 512; s; s >>= 1) { if (tid < s) red[tid] = fmaxf(red[tid], red[tid + s]); __syncthreads(); }
    m = red[0]; __syncthreads();

    float e0 = __expf(row[tid] - m);
    float e1 = __expf(row[tid + 1024] - m);
    red[tid] = e0 + e1; __syncthreads();
    for (int s = 512; s; s >>= 1) { if (tid < s) red[tid] += red[tid + s]; __syncthreads(); }
    float inv = 1.f / red[0];
    row[tid] = e0 * inv;
    row[tid + 1024] = e1 * inv;
}

// ---------------------------------------------------------------------------
// Kernel 4a: context partials from fp16 A. grid (NCH, B), block 256; 32 rows.
// ---------------------------------------------------------------------------
__global__ void context_part_kernel(const float* __restrict__ w) {
    int sc = blockIdx.x, b = blockIdx.y;
    __shared__ float ws[32];
    int tid = threadIdx.x;
    if (tid < 32) ws[tid] = w[(size_t)b * Ss + sc * 32 + tid];
    __syncthreads();
    int h4 = tid * 4;
    const __half* Ab = g_Ah + ((size_t)b * Ss + sc * 32) * Hh + h4;
    float4 acc = {0.f, 0.f, 0.f, 0.f};
    #pragma unroll 8
    for (int s = 0; s < 32; s++) {
        uint2 raw = __ldg((const uint2*)(Ab + (size_t)s * Hh));
        float2 lo = __half22float2(*(const __half2*)&raw.x);
        float2 hi = __half22float2(*(const __half2*)&raw.y);
        float wv = ws[s];
        acc.x += wv * lo.x; acc.y += wv * lo.y; acc.z += wv * hi.x; acc.w += wv * hi.y;
    }
    *(float4*)(g_ctx_part + ((size_t)(b * NCH + sc) * Hh) + h4) = acc;
}

// Kernel 4b: reduce partials
__global__ void context_reduce_kernel(float* __restrict__ ctx) {
    int b = blockIdx.x;
    int h4 = threadIdx.x * 4;
    float4 s = {0.f, 0.f, 0.f, 0.f};
    #pragma unroll
    for (int j = 0; j < NCH; j++) {
        float4 p = *(const float4*)(g_ctx_part + ((size_t)(b * NCH + j) * Hh) + h4);
        s.x += p.x; s.y += p.y; s.z += p.z; s.w += p.w;
    }
    *(float4*)(ctx + (size_t)b * Hh + h4) = s;
}

// ---------------------------------------------------------------------------
extern "C" void kernel_launch(void* const* d_in, const int* in_sizes, int n_in,
                              void* d_out, int out_size) {
    const float* h    = (const float*)d_in[0];
    // d_in[1] = c (unused)
    const float* a    = (const float*)d_in[2];
    const float* W    = (const float*)d_in[3];
    const float* bias = (const float*)d_in[4];
    const float* vW   = (const float*)d_in[5];

    float* ctx_out  = (float*)d_out;              // (B,1,H)
    float* attn_out = (float*)d_out + Bb * Hh;    // (B,S)

    static bool attr_set = false;
    if (!attr_set) {
        cudaFuncSetAttribute(scores_mma, cudaFuncAttributeMaxDynamicSharedMemorySize, SC_SMEM);
        attr_set = true;
    }

    prep_kernel<<<NCONV_A + NCONV_W + NQ + NZ, 256>>>(a, W, h, bias, attn_out);
    scores_mma<<<dim3(Mm / 128, Hh / 128), 256, SC_SMEM>>>(vW, attn_out);
    softmax_kernel<<<Bb, 1024>>>(attn_out);
    context_part_kernel<<<dim3(NCH, Bb), 256>>>(attn_out);
    context_reduce_kernel<<<Bb, 256>>>(ctx_out);
}

// round 17
// speedup vs baseline: 1.2857x; 1.2857x over previous
#include <cuda_runtime.h>
#include <cuda_fp16.h>
#include <math_constants.h>
#include <cstdint>

#define Bb 16
#define Ss 2048
#define Hh 1024
#define Mm (Bb * Ss)   // 32768

#define NCH 64           // context S-chunks
__device__ float g_q[Bb * Hh];
__device__ float g_ctx_part[16 * NCH * 1024];
__device__ __half g_Ah[(size_t)Mm * Hh];   // fp16 copy of encoder_outputs (64 MB)
__device__ __half g_Wh[(size_t)Hh * Hh];   // fp16 copy of Wa (2 MB)

// ---------------------------------------------------------------- helpers
__device__ __forceinline__ uint32_t smem_u32(const void* p) {
    uint32_t a;
    asm("{ .reg .u64 t; cvta.to.shared.u64 t, %1; cvt.u32.u64 %0, t; }" : "=r"(a) : "l"(p));
    return a;
}
__device__ __forceinline__ void cp_async16(uint32_t dst, const void* src) {
    asm volatile("cp.async.cg.shared.global [%0], [%1], 16;" :: "r"(dst), "l"(src));
}
__device__ __forceinline__ void cp_commit() { asm volatile("cp.async.commit_group;"); }
__device__ __forceinline__ void cp_wait1()  { asm volatile("cp.async.wait_group 1;"); }
__device__ __forceinline__ void cp_wait0()  { asm volatile("cp.async.wait_group 0;"); }

__device__ __forceinline__ void ldsm_x4(uint32_t* r, uint32_t addr) {
    asm volatile("ldmatrix.sync.aligned.m8n8.x4.shared.b16 {%0,%1,%2,%3}, [%4];"
                 : "=r"(r[0]), "=r"(r[1]), "=r"(r[2]), "=r"(r[3]) : "r"(addr));
}

__device__ __forceinline__ void mma_fp16(float* d, const uint32_t* a, uint32_t b0, uint32_t b1) {
    asm volatile(
        "mma.sync.aligned.m16n8k16.row.col.f32.f16.f16.f32 "
        "{%0,%1,%2,%3}, {%4,%5,%6,%7}, {%8,%9}, {%0,%1,%2,%3};"
        : "+f"(d[0]), "+f"(d[1]), "+f"(d[2]), "+f"(d[3])
        : "r"(a[0]), "r"(a[1]), "r"(a[2]), "r"(a[3]), "r"(b0), "r"(b1));
}

// ---------------------------------------------------------------------------
// Kernel 0: fused prep — convert A & Wa to fp16, compute q, zero scores.
// Flattened grid: [0, Mm) convA; [Mm, Mm+Hh) convW; then q and zero blocks.
// ---------------------------------------------------------------------------
#define NCONV_A Mm                 // 32768 blocks
#define NCONV_W Hh                 // 1024 blocks
#define NQ (Bb * (Hh / 8))         // 2048 blocks
#define NZ (Bb * 2)                // 32 blocks

__global__ void prep_kernel(const float* __restrict__ A,
                            const float* __restrict__ W,
                            const float* __restrict__ h,
                            const float* __restrict__ bias,
                            float* __restrict__ scores) {
    int bid = blockIdx.x;
    if (bid < NCONV_A) {
        size_t i = ((size_t)bid * 256 + threadIdx.x) * 4;
        float4 v = *(const float4*)(A + i);
        *(__half2*)(g_Ah + i)     = __floats2half2_rn(v.x, v.y);
        *(__half2*)(g_Ah + i + 2) = __floats2half2_rn(v.z, v.w);
        return;
    }
    bid -= NCONV_A;
    if (bid < NCONV_W) {
        int idx = bid * 256 + threadIdx.x;
        int row = idx >> 8;
        int col = (idx & 255) * 4;
        float4 v = *(const float4*)(W + (size_t)row * (2 * Hh) + Hh + col);
        *(__half2*)(g_Wh + (size_t)row * Hh + col)     = __floats2half2_rn(v.x, v.y);
        *(__half2*)(g_Wh + (size_t)row * Hh + col + 2) = __floats2half2_rn(v.z, v.w);
        return;
    }
    bid -= NCONV_W;
    if (bid < NQ) {
        int b = bid >> 7;              // /(Hh/8)
        int y = bid & 127;
        __shared__ float hs[Hh];
        for (int i = threadIdx.x; i < Hh; i += blockDim.x) hs[i] = h[b * Hh + i];
        __syncthreads();
        int warp = threadIdx.x >> 5, lane = threadIdx.x & 31;
        int o = y * 8 + warp;
        const float* Wrow = W + (size_t)o * (2 * Hh);
        float acc = 0.f;
        #pragma unroll 8
        for (int k = lane; k < Hh; k += 32) acc += hs[k] * Wrow[k];
        #pragma unroll
        for (int off = 16; off; off >>= 1) acc += __shfl_xor_sync(0xffffffffu, acc, off);
        if (lane == 0) g_q[b * Hh + o] = acc + bias[o];
        return;
    }
    bid -= NQ;
    {   // zero scores
        int b = bid >> 1, part = bid & 1;
        size_t base = (size_t)b * Ss + part * 1024;
        for (int i = threadIdx.x; i < 1024; i += blockDim.x) scores[base + i] = 0.f;
    }
}

// ---------------------------------------------------------------------------
// Kernel 2: fused scores GEMM, fp16 mma.sync m16n8k16 — R14/R15 measured best.
// CTA = 256 threads (8 warps), tile 128x128, warp tile 32x64 (4x2).
// BK=32 halves, 2-stage cp.async, PADH=40 (verified LDSM conflict-free).
// Epilogue: relu(+q)*v row-reduction, atomicAdd row partials.
// ---------------------------------------------------------------------------
#define BKI 32
#define PADH 40
#define NIT (Hh / BKI)                 // 32
#define TAH (128 * PADH)               // tile halves per matrix (5120)
#define TA_B (TAH * 2)                 // 10240 bytes
#define STAGE_B (2 * TA_B)             // A + B (20480 bytes)
#define SC_SMEM (2 * STAGE_B)          // 40960 bytes

__global__ void __launch_bounds__(256, 2)
scores_mma(const float* __restrict__ v,
           float* __restrict__ out_scores) {
    extern __shared__ __half smh[];
    __shared__ float s_q[128];
    __shared__ float s_v[128];

    const int tid  = threadIdx.x;
    const int wid  = tid >> 5, lane = tid & 31;
    const int g    = lane >> 2, t = lane & 3;
    const int bm   = blockIdx.x;          // m block (128 rows) — fastest
    const int bn   = blockIdx.y;          // n block (128 cols)
    const int b    = (bm * 128) >> 11;    // batch
    const int wm   = (wid & 3) * 32;      // warp m offset
    const int wn   = (wid >> 2) * 64;     // warp n offset

    if (tid < 128) {
        s_q[tid] = g_q[b * Hh + bn * 128 + tid];
        s_v[tid] = v[bn * 128 + tid];
    }

    const uint32_t smBase = smem_u32(smh);

    const int r0 = tid >> 2, ch = tid & 3;
    const __half* aG = g_Ah + (size_t)(bm * 128 + r0) * Hh + ch * 8;
    const __half* bG = g_Wh + (size_t)(bn * 128 + r0) * Hh + ch * 8;
    const uint32_t aSm = smBase + r0 * (PADH * 2) + ch * 16;
    const uint32_t bSm = smBase + TA_B + r0 * (PADH * 2) + ch * 16;

    const uint32_t aAddr = smBase + (wm + (lane & 15)) * (PADH * 2) + (lane >> 4) * 16;
    const uint32_t bAddr = smBase + TA_B + (wn + (lane & 15)) * (PADH * 2) + (lane >> 4) * 16;

    auto load_stage = [&](int s, int k0) {
        const uint32_t so = s * STAGE_B;
        const __half* ag = aG + k0;
        const __half* bg = bG + k0;
        cp_async16(aSm + so,                     ag);
        cp_async16(aSm + so + 64 * (PADH * 2),  ag + (size_t)64 * Hh);
        cp_async16(bSm + so,                     bg);
        cp_async16(bSm + so + 64 * (PADH * 2),  bg + (size_t)64 * Hh);
        cp_commit();
    };

    float acc[2][8][4] = {};

    load_stage(0, 0);

    for (int it = 0; it < NIT; it++) {
        const int buf = it & 1;
        if (it + 1 < NIT) { load_stage(buf ^ 1, (it + 1) * BKI); cp_wait1(); }
        else              { cp_wait0(); }
        __syncthreads();

        const uint32_t aB = aAddr + buf * STAGE_B;
        const uint32_t bB = bAddr + buf * STAGE_B;

        #pragma unroll
        for (int ks = 0; ks < 2; ks++) {
            const uint32_t ko = ks * 32;           // 16 halves per k-step
            uint32_t a0[4], a1[4], b0[4], b1[4], b2[4], b3[4];
            ldsm_x4(a0, aB + ko);
            ldsm_x4(a1, aB + ko + 16 * (PADH * 2));
            ldsm_x4(b0, bB + ko);
            ldsm_x4(b1, bB + ko + 16 * (PADH * 2));
            ldsm_x4(b2, bB + ko + 32 * (PADH * 2));
            ldsm_x4(b3, bB + ko + 48 * (PADH * 2));

            mma_fp16(acc[0][0], a0, b0[0], b0[2]);  mma_fp16(acc[1][0], a1, b0[0], b0[2]);
            mma_fp16(acc[0][1], a0, b0[1], b0[3]);  mma_fp16(acc[1][1], a1, b0[1], b0[3]);
            mma_fp16(acc[0][2], a0, b1[0], b1[2]);  mma_fp16(acc[1][2], a1, b1[0], b1[2]);
            mma_fp16(acc[0][3], a0, b1[1], b1[3]);  mma_fp16(acc[1][3], a1, b1[1], b1[3]);
            mma_fp16(acc[0][4], a0, b2[0], b2[2]);  mma_fp16(acc[1][4], a1, b2[0], b2[2]);
            mma_fp16(acc[0][5], a0, b2[1], b2[3]);  mma_fp16(acc[1][5], a1, b2[1], b2[3]);
            mma_fp16(acc[0][6], a0, b3[0], b3[2]);  mma_fp16(acc[1][6], a1, b3[0], b3[2]);
            mma_fp16(acc[0][7], a0, b3[1], b3[3]);  mma_fp16(acc[1][7], a1, b3[1], b3[3]);
        }
        __syncthreads();
    }

    // epilogue: relu(+q)*v, reduce cols
    float rs[2][2] = {};
    #pragma unroll
    for (int j = 0; j < 8; j++) {
        const int nl = wn + j * 8 + 2 * t;
        const float q0 = s_q[nl], q1 = s_q[nl + 1];
        const float v0 = s_v[nl], v1 = s_v[nl + 1];
        #pragma unroll
        for (int i = 0; i < 2; i++) {
            rs[i][0] += fmaxf(acc[i][j][0] + q0, 0.f) * v0 + fmaxf(acc[i][j][1] + q1, 0.f) * v1;
            rs[i][1] += fmaxf(acc[i][j][2] + q0, 0.f) * v0 + fmaxf(acc[i][j][3] + q1, 0.f) * v1;
        }
    }
    #pragma unroll
    for (int off = 1; off < 4; off <<= 1) {
        #pragma unroll
        for (int i = 0; i < 2; i++) {
            rs[i][0] += __shfl_xor_sync(0xffffffffu, rs[i][0], off);
            rs[i][1] += __shfl_xor_sync(0xffffffffu, rs[i][1], off);
        }
    }
    if (t == 0) {
        const int rowb = bm * 128 + wm;
        #pragma unroll
        for (int i = 0; i < 2; i++) {
            atomicAdd(&out_scores[rowb + i * 16 + g    ], rs[i][0]);
            atomicAdd(&out_scores[rowb + i * 16 + g + 8], rs[i][1]);
        }
    }
}

// ---------------------------------------------------------------------------
// Kernel 3: in-place softmax over S per batch. grid 16, block 1024.
// ---------------------------------------------------------------------------
__global__ void softmax_kernel(float* __restrict__ w) {
    int b = blockIdx.x;
    float* row = w + (size_t)b * Ss;
    __shared__ float red[1024];
    int tid = threadIdx.x;

    float m = fmaxf(row[tid], row[tid + 1024]);
    red[tid] = m; __syncthreads();
    for (int s = 512; s; s >>= 1) { if (tid < s) red[tid] = fmaxf(red[tid], red[tid + s]); __syncthreads(); }
    m = red[0]; __syncthreads();

    float e0 = __expf(row[tid] - m);
    float e1 = __expf(row[tid + 1024] - m);
    red[tid] = e0 + e1; __syncthreads();
    for (int s = 512; s; s >>= 1) { if (tid < s) red[tid] += red[tid + s]; __syncthreads(); }
    float inv = 1.f / red[0];
    row[tid] = e0 * inv;
    row[tid + 1024] = e1 * inv;
}

// ---------------------------------------------------------------------------
// Kernel 4a: context partials from fp16 A. grid (NCH, B), block 256; 32 rows.
// ---------------------------------------------------------------------------
__global__ void context_part_kernel(const float* __restrict__ w) {
    int sc = blockIdx.x, b = blockIdx.y;
    __shared__ float ws[32];
    int tid = threadIdx.x;
    if (tid < 32) ws[tid] = w[(size_t)b * Ss + sc * 32 + tid];
    __syncthreads();
    int h4 = tid * 4;
    const __half* Ab = g_Ah + ((size_t)b * Ss + sc * 32) * Hh + h4;
    float4 acc = {0.f, 0.f, 0.f, 0.f};
    #pragma unroll 8
    for (int s = 0; s < 32; s++) {
        uint2 raw = __ldg((const uint2*)(Ab + (size_t)s * Hh));
        float2 lo = __half22float2(*(const __half2*)&raw.x);
        float2 hi = __half22float2(*(const __half2*)&raw.y);
        float wv = ws[s];
        acc.x += wv * lo.x; acc.y += wv * lo.y; acc.z += wv * hi.x; acc.w += wv * hi.y;
    }
    *(float4*)(g_ctx_part + ((size_t)(b * NCH + sc) * Hh) + h4) = acc;
}

// Kernel 4b: reduce partials
__global__ void context_reduce_kernel(float* __restrict__ ctx) {
    int b = blockIdx.x;
    int h4 = threadIdx.x * 4;
    float4 s = {0.f, 0.f, 0.f, 0.f};
    #pragma unroll
    for (int j = 0; j < NCH; j++) {
        float4 p = *(const float4*)(g_ctx_part + ((size_t)(b * NCH + j) * Hh) + h4);
        s.x += p.x; s.y += p.y; s.z += p.z; s.w += p.w;
    }
    *(float4*)(ctx + (size_t)b * Hh + h4) = s;
}

// ---------------------------------------------------------------------------
extern "C" void kernel_launch(void* const* d_in, const int* in_sizes, int n_in,
                              void* d_out, int out_size) {
    const float* h    = (const float*)d_in[0];
    // d_in[1] = c (unused)
    const float* a    = (const float*)d_in[2];
    const float* W    = (const float*)d_in[3];
    const float* bias = (const float*)d_in[4];
    const float* vW   = (const float*)d_in[5];

    float* ctx_out  = (float*)d_out;              // (B,1,H)
    float* attn_out = (float*)d_out + Bb * Hh;    // (B,S)

    static bool attr_set = false;
    if (!attr_set) {
        cudaFuncSetAttribute(scores_mma, cudaFuncAttributeMaxDynamicSharedMemorySize, SC_SMEM);
        attr_set = true;
    }

    prep_kernel<<<NCONV_A + NCONV_W + NQ + NZ, 256>>>(a, W, h, bias, attn_out);
    scores_mma<<<dim3(Mm / 128, Hh / 128), 256, SC_SMEM>>>(vW, attn_out);
    softmax_kernel<<<Bb, 1024>>>(attn_out);
    context_part_kernel<<<dim3(NCH, Bb), 256>>>(attn_out);
    context_reduce_kernel<<<Bb, 256>>>(ctx_out);
}